// round 5
// baseline (speedup 1.0000x reference)
#include <cuda_runtime.h>
#include <cuda_bf16.h>

// Problem constants (fixed shapes)
#define BATCH 4
#define CIN   64
#define HNUM  96
#define WNUM  96
#define G     8
#define OG    8
#define OGH   4            // channels handled per block
#define IG    8
#define KW    7
#define PAD   3
#define PLANE (HNUM * WNUM)

// Tiling: 96 threads = 12 rows x 8 thread-cols, each thread owns 4 adjacent px.
#define TH 12
#define TW 32
#define TCN 8
#define PXW 4
#define NTHREADS 96
#define HH  (TH + KW - 1)   // 18
#define HWD (TW + KW - 1)   // 38
#define KVSTR 80            // floats per row: 38 px * 2 (k,v interleaved), pad 80

__global__ __launch_bounds__(NTHREADS)
void attn_fused_kernel(const float* __restrict__ x,
                       const float* __restrict__ wq,
                       const float* __restrict__ wk,
                       const float* __restrict__ wv,
                       const float* __restrict__ h_emb,
                       const float* __restrict__ w_emb,
                       float* __restrict__ out)
{
    // k,v interleaved per pixel for LDS.128: [ch][row][2*col + {k,v}]
    __shared__ __align__(16) float kv_s[OGH][HH][KVSTR];   // 23.0 KB
    __shared__ float  wq_s[OGH * IG];
    __shared__ float2 wkv_s[OGH * IG];
    __shared__ float  emb_s[OGH * KW];

    const int tid  = threadIdx.x;
    const int bz   = blockIdx.z;       // ((b*8+g)*2 + half)
    const int half = bz & 1;
    const int g    = (bz >> 1) & 7;
    const int b    = bz >> 4;
    const int h0   = blockIdx.y * TH;
    const int w0   = blockIdx.x * TW;

    if (tid < 32) {
        const int wi = g * 64 + half * 32 + tid;
        wq_s[tid]  = wq[wi];
        wkv_s[tid] = make_float2(wk[wi], wv[wi]);
    } else if (tid >= 32 && tid < 60) {
        const float* ep = half ? w_emb : h_emb;
        emb_s[tid - 32] = ep[g * 28 + (tid - 32)];
    }
    __syncthreads();

    const float* xg = x + (size_t)(b * CIN + g * IG) * PLANE;
    const int cbase = half * OGH;

    // --- phase 1: grouped 1x1 conv k,v over haloed tile -> interleaved SMEM ---
    for (int p = tid; p < HH * HWD; p += NTHREADS) {
        const int yy = p / HWD;
        const int xx = p - yy * HWD;
        const int gy = h0 + yy - PAD;
        const int gx = w0 + xx - PAD;
        const bool inb = ((unsigned)gy < HNUM) & ((unsigned)gx < WNUM);
        const float* xb = xg + gy * WNUM + gx;
        float xi[IG];
        #pragma unroll
        for (int i = 0; i < IG; i++)
            xi[i] = inb ? __ldg(xb + i * PLANE) : 0.0f;
        #pragma unroll
        for (int c = 0; c < OGH; c++) {
            float kc = 0.0f, vc = 0.0f;
            #pragma unroll
            for (int i = 0; i < IG; i++) {
                const float2 w2 = wkv_s[c * IG + i];
                kc = fmaf(w2.x, xi[i], kc);
                vc = fmaf(w2.y, xi[i], vc);
            }
            *(float2*)&kv_s[c][yy][2 * xx] = make_float2(kc, vc);
        }
    }
    __syncthreads();

    // --- phase 2: each thread owns 4 adjacent pixels, 4 channels ---
    const int tc = tid & (TCN - 1);
    const int ty = tid >> 3;
    const int x_ = PXW * tc;           // first pixel col within tile
    const int gh = h0 + ty;
    const int gw = w0 + x_;

    const float LOG2E = 1.4426950408889634f;

    // Precompute q (scaled by log2e) for 4 channels x 4 px, then drop xi.
    float qs[OGH][PXW];
    {
        float4 xi[IG];
        const float* xb = xg + gh * WNUM + gw;
        #pragma unroll
        for (int i = 0; i < IG; i++)
            xi[i] = __ldg((const float4*)(xb + i * PLANE));
        #pragma unroll
        for (int c = 0; c < OGH; c++) {
            float q0 = 0.f, q1 = 0.f, q2 = 0.f, q3 = 0.f;
            #pragma unroll
            for (int i = 0; i < IG; i++) {
                const float wv_ = wq_s[c * IG + i];
                q0 = fmaf(wv_, xi[i].x, q0);
                q1 = fmaf(wv_, xi[i].y, q1);
                q2 = fmaf(wv_, xi[i].z, q2);
                q3 = fmaf(wv_, xi[i].w, q3);
            }
            qs[c][0] = q0 * LOG2E; qs[c][1] = q1 * LOG2E;
            qs[c][2] = q2 * LOG2E; qs[c][3] = q3 * LOG2E;
        }
    }

    float* op = out + ((size_t)(b * CIN + g * OG + cbase) * HNUM + gh) * WNUM + gw;

    if (half == 0) {
        // channels 0..3: emb varies along patch ROW (di)
        #pragma unroll 1
        for (int c = 0; c < OGH; c++) {
            float ssum[PXW] = {0.f, 0.f, 0.f, 0.f};
            float acc[PXW]  = {0.f, 0.f, 0.f, 0.f};
            #pragma unroll
            for (int di = 0; di < KW; di++) {
                const float eh = emb_s[c * KW + di];
                float qe[PXW];
                #pragma unroll
                for (int p = 0; p < PXW; p++) qe[p] = qs[c][p] * eh;

                const float4* rp = (const float4*)&kv_s[c][ty + di][2 * x_];
                float4 a0 = rp[0], a1 = rp[1], a2 = rp[2], a3 = rp[3], a4 = rp[4];
                float ka[10] = {a0.x, a0.z, a1.x, a1.z, a2.x, a2.z, a3.x, a3.z, a4.x, a4.z};
                float va[10] = {a0.y, a0.w, a1.y, a1.w, a2.y, a2.w, a3.y, a3.w, a4.y, a4.w};
                #pragma unroll
                for (int p = 0; p < PXW; p++) {
                    #pragma unroll
                    for (int dj = 0; dj < KW; dj++) {
                        float e;
                        asm("ex2.approx.f32 %0, %1;" : "=f"(e)
                            : "f"(fmaf(qs[c][p], ka[p + dj], qe[p])));
                        ssum[p] += e;
                        acc[p] = fmaf(e, va[p + dj], acc[p]);
                    }
                }
            }
            float4 o = make_float4(__fdividef(acc[0], ssum[0]),
                                   __fdividef(acc[1], ssum[1]),
                                   __fdividef(acc[2], ssum[2]),
                                   __fdividef(acc[3], ssum[3]));
            *(float4*)&op[(size_t)c * PLANE] = o;
        }
    } else {
        // channels 4..7: emb varies along patch COL (dj)
        #pragma unroll 1
        for (int c = 0; c < OGH; c++) {
            float qe[PXW][KW];
            #pragma unroll
            for (int p = 0; p < PXW; p++)
                #pragma unroll
                for (int t = 0; t < KW; t++)
                    qe[p][t] = qs[c][p] * emb_s[c * KW + t];

            float ssum[PXW] = {0.f, 0.f, 0.f, 0.f};
            float acc[PXW]  = {0.f, 0.f, 0.f, 0.f};
            #pragma unroll
            for (int di = 0; di < KW; di++) {
                const float4* rp = (const float4*)&kv_s[c][ty + di][2 * x_];
                float4 a0 = rp[0], a1 = rp[1], a2 = rp[2], a3 = rp[3], a4 = rp[4];
                float ka[10] = {a0.x, a0.z, a1.x, a1.z, a2.x, a2.z, a3.x, a3.z, a4.x, a4.z};
                float va[10] = {a0.y, a0.w, a1.y, a1.w, a2.y, a2.w, a3.y, a3.w, a4.y, a4.w};
                #pragma unroll
                for (int p = 0; p < PXW; p++) {
                    #pragma unroll
                    for (int dj = 0; dj < KW; dj++) {
                        float e;
                        asm("ex2.approx.f32 %0, %1;" : "=f"(e)
                            : "f"(fmaf(qs[c][p], ka[p + dj], qe[p][dj])));
                        ssum[p] += e;
                        acc[p] = fmaf(e, va[p + dj], acc[p]);
                    }
                }
            }
            float4 o = make_float4(__fdividef(acc[0], ssum[0]),
                                   __fdividef(acc[1], ssum[1]),
                                   __fdividef(acc[2], ssum[2]),
                                   __fdividef(acc[3], ssum[3]));
            *(float4*)&op[(size_t)c * PLANE] = o;
        }
    }
}

extern "C" void kernel_launch(void* const* d_in, const int* in_sizes, int n_in,
                              void* d_out, int out_size)
{
    const float* x     = (const float*)d_in[0];
    const float* wq    = (const float*)d_in[1];
    const float* wk    = (const float*)d_in[2];
    const float* wv    = (const float*)d_in[3];
    const float* h_emb = (const float*)d_in[4];
    const float* w_emb = (const float*)d_in[5];
    float* out = (float*)d_out;

    dim3 grid(WNUM / TW, HNUM / TH, BATCH * G * 2);  // (3, 8, 64) = 1536 blocks
    dim3 block(NTHREADS);
    attn_fused_kernel<<<grid, block>>>(x, wq, wk, wv, h_emb, w_emb, out);
}

// round 6
// speedup vs baseline: 1.1063x; 1.1063x over previous
#include <cuda_runtime.h>
#include <cuda_bf16.h>

// Problem constants (fixed shapes)
#define BATCH 4
#define CIN   64
#define HNUM  96
#define WNUM  96
#define G     8
#define OG    8
#define OGH   4            // channels handled per block
#define IG    8
#define KW    7
#define PAD   3
#define PLANE (HNUM * WNUM)

// Tiling: 192 threads = 12 ty x 16 tc; each thread owns a 2x2 pixel quad.
#define TH 24
#define TW 32
#define TCN 16
#define NTHREADS 192
#define HH  (TH + KW - 1)   // 30
#define HWD (TW + KW - 1)   // 38
#define KVSTR 76            // floats per row: 38 px * 2 (k,v). 304B = 19*16B aligned.

__global__ __launch_bounds__(NTHREADS)
void attn_fused_kernel(const float* __restrict__ x,
                       const float* __restrict__ wq,
                       const float* __restrict__ wk,
                       const float* __restrict__ wv,
                       const float* __restrict__ h_emb,
                       const float* __restrict__ w_emb,
                       float* __restrict__ out)
{
    // k,v interleaved per pixel for LDS.128: [ch][row][2*col + {k,v}]
    __shared__ __align__(16) float kv_s[OGH][HH][KVSTR];   // 4*30*76*4 = 35.6 KB
    __shared__ float  wq_s[OGH * IG];
    __shared__ float2 wkv_s[OGH * IG];
    __shared__ float  emb_s[OGH * KW];

    const int tid  = threadIdx.x;
    const int bz   = blockIdx.z;       // ((b*8+g)*2 + half)
    const int half = bz & 1;
    const int g    = (bz >> 1) & 7;
    const int b    = bz >> 4;
    const int h0   = blockIdx.y * TH;
    const int w0   = blockIdx.x * TW;

    if (tid < 32) {
        const int wi = g * 64 + half * 32 + tid;
        wq_s[tid]  = wq[wi];
        wkv_s[tid] = make_float2(wk[wi], wv[wi]);
    } else if (tid >= 32 && tid < 60) {
        const float* ep = half ? w_emb : h_emb;
        emb_s[tid - 32] = ep[g * 28 + (tid - 32)];
    }
    __syncthreads();

    const float* xg = x + (size_t)(b * CIN + g * IG) * PLANE;
    const int cbase = half * OGH;

    // --- phase 1: grouped 1x1 conv k,v over haloed tile -> interleaved SMEM ---
    for (int p = tid; p < HH * HWD; p += NTHREADS) {
        const int yy = p / HWD;
        const int xx = p - yy * HWD;
        const int gy = h0 + yy - PAD;
        const int gx = w0 + xx - PAD;
        const bool inb = ((unsigned)gy < HNUM) & ((unsigned)gx < WNUM);
        const float* xb = xg + gy * WNUM + gx;
        float xi[IG];
        #pragma unroll
        for (int i = 0; i < IG; i++)
            xi[i] = inb ? __ldg(xb + i * PLANE) : 0.0f;
        #pragma unroll
        for (int c = 0; c < OGH; c++) {
            float kc = 0.0f, vc = 0.0f;
            #pragma unroll
            for (int i = 0; i < IG; i++) {
                const float2 w2 = wkv_s[c * IG + i];
                kc = fmaf(w2.x, xi[i], kc);
                vc = fmaf(w2.y, xi[i], vc);
            }
            *(float2*)&kv_s[c][yy][2 * xx] = make_float2(kc, vc);
        }
    }
    __syncthreads();

    // --- phase 2: each thread owns a 2x2 quad of pixels, 4 channels ---
    const int tc = tid & (TCN - 1);
    const int ty = tid >> 4;           // 0..11
    const int x_ = 2 * tc;             // pixel col in tile
    const int y0 = 2 * ty;             // first pixel row in tile
    const int gh = h0 + y0;
    const int gw = w0 + x_;

    const float LOG2E = 1.4426950408889634f;

    // q (scaled by log2e) for 4 channels x 4 px. p = 2*h + w.
    float qs[OGH][4];
    {
        float2 xi0[IG], xi1[IG];
        const float* xb = xg + gh * WNUM + gw;
        #pragma unroll
        for (int i = 0; i < IG; i++) {
            xi0[i] = __ldg((const float2*)(xb + i * PLANE));
            xi1[i] = __ldg((const float2*)(xb + i * PLANE + WNUM));
        }
        #pragma unroll
        for (int c = 0; c < OGH; c++) {
            float q0 = 0.f, q1 = 0.f, q2 = 0.f, q3 = 0.f;
            #pragma unroll
            for (int i = 0; i < IG; i++) {
                const float wv_ = wq_s[c * IG + i];
                q0 = fmaf(wv_, xi0[i].x, q0);
                q1 = fmaf(wv_, xi0[i].y, q1);
                q2 = fmaf(wv_, xi1[i].x, q2);
                q3 = fmaf(wv_, xi1[i].y, q3);
            }
            qs[c][0] = q0 * LOG2E; qs[c][1] = q1 * LOG2E;
            qs[c][2] = q2 * LOG2E; qs[c][3] = q3 * LOG2E;
        }
    }

    float* op = out + ((size_t)(b * CIN + g * OG + cbase) * HNUM + gh) * WNUM + gw;

    if (half == 0) {
        // channels 0..3: emb varies along patch ROW (di)
        #pragma unroll 1
        for (int c = 0; c < OGH; c++) {
            float ss[4] = {0.f, 0.f, 0.f, 0.f};
            float ac[4] = {0.f, 0.f, 0.f, 0.f};
            #pragma unroll
            for (int di = 0; di < KW + 1; di++) {     // 8 halo rows
                const float4* rp = (const float4*)&kv_s[c][y0 + di][2 * x_];
                float4 a0 = rp[0], a1 = rp[1], a2 = rp[2], a3 = rp[3];
                float ka[8] = {a0.x, a0.z, a1.x, a1.z, a2.x, a2.z, a3.x, a3.z};
                float va[8] = {a0.y, a0.w, a1.y, a1.w, a2.y, a2.w, a3.y, a3.w};
                if (di < KW) {      // pixel row 0: tap row di, emb[di]
                    const float eh = emb_s[c * KW + di];
                    const float qe0 = qs[c][0] * eh, qe1 = qs[c][1] * eh;
                    #pragma unroll
                    for (int dj = 0; dj < KW; dj++) {
                        float e0;
                        asm("ex2.approx.f32 %0, %1;" : "=f"(e0)
                            : "f"(fmaf(qs[c][0], ka[dj], qe0)));
                        ss[0] += e0; ac[0] = fmaf(e0, va[dj], ac[0]);
                        float e1;
                        asm("ex2.approx.f32 %0, %1;" : "=f"(e1)
                            : "f"(fmaf(qs[c][1], ka[dj + 1], qe1)));
                        ss[1] += e1; ac[1] = fmaf(e1, va[dj + 1], ac[1]);
                    }
                }
                if (di >= 1) {      // pixel row 1: tap row di-1, emb[di-1]
                    const float eh = emb_s[c * KW + di - 1];
                    const float qe2 = qs[c][2] * eh, qe3 = qs[c][3] * eh;
                    #pragma unroll
                    for (int dj = 0; dj < KW; dj++) {
                        float e2;
                        asm("ex2.approx.f32 %0, %1;" : "=f"(e2)
                            : "f"(fmaf(qs[c][2], ka[dj], qe2)));
                        ss[2] += e2; ac[2] = fmaf(e2, va[dj], ac[2]);
                        float e3;
                        asm("ex2.approx.f32 %0, %1;" : "=f"(e3)
                            : "f"(fmaf(qs[c][3], ka[dj + 1], qe3)));
                        ss[3] += e3; ac[3] = fmaf(e3, va[dj + 1], ac[3]);
                    }
                }
            }
            *(float2*)&op[(size_t)c * PLANE] =
                make_float2(__fdividef(ac[0], ss[0]), __fdividef(ac[1], ss[1]));
            *(float2*)&op[(size_t)c * PLANE + WNUM] =
                make_float2(__fdividef(ac[2], ss[2]), __fdividef(ac[3], ss[3]));
        }
    } else {
        // channels 4..7: emb varies along patch COL (dj)
        #pragma unroll 1
        for (int c = 0; c < OGH; c++) {
            float qe[4][KW];
            #pragma unroll
            for (int p = 0; p < 4; p++)
                #pragma unroll
                for (int t = 0; t < KW; t++)
                    qe[p][t] = qs[c][p] * emb_s[c * KW + t];

            float ss[4] = {0.f, 0.f, 0.f, 0.f};
            float ac[4] = {0.f, 0.f, 0.f, 0.f};
            #pragma unroll
            for (int di = 0; di < KW + 1; di++) {
                const float4* rp = (const float4*)&kv_s[c][y0 + di][2 * x_];
                float4 a0 = rp[0], a1 = rp[1], a2 = rp[2], a3 = rp[3];
                float ka[8] = {a0.x, a0.z, a1.x, a1.z, a2.x, a2.z, a3.x, a3.z};
                float va[8] = {a0.y, a0.w, a1.y, a1.w, a2.y, a2.w, a3.y, a3.w};
                if (di < KW) {
                    #pragma unroll
                    for (int dj = 0; dj < KW; dj++) {
                        float e0;
                        asm("ex2.approx.f32 %0, %1;" : "=f"(e0)
                            : "f"(fmaf(qs[c][0], ka[dj], qe[0][dj])));
                        ss[0] += e0; ac[0] = fmaf(e0, va[dj], ac[0]);
                        float e1;
                        asm("ex2.approx.f32 %0, %1;" : "=f"(e1)
                            : "f"(fmaf(qs[c][1], ka[dj + 1], qe[1][dj])));
                        ss[1] += e1; ac[1] = fmaf(e1, va[dj + 1], ac[1]);
                    }
                }
                if (di >= 1) {
                    #pragma unroll
                    for (int dj = 0; dj < KW; dj++) {
                        float e2;
                        asm("ex2.approx.f32 %0, %1;" : "=f"(e2)
                            : "f"(fmaf(qs[c][2], ka[dj], qe[2][dj])));
                        ss[2] += e2; ac[2] = fmaf(e2, va[dj], ac[2]);
                        float e3;
                        asm("ex2.approx.f32 %0, %1;" : "=f"(e3)
                            : "f"(fmaf(qs[c][3], ka[dj + 1], qe[3][dj])));
                        ss[3] += e3; ac[3] = fmaf(e3, va[dj + 1], ac[3]);
                    }
                }
            }
            *(float2*)&op[(size_t)c * PLANE] =
                make_float2(__fdividef(ac[0], ss[0]), __fdividef(ac[1], ss[1]));
            *(float2*)&op[(size_t)c * PLANE + WNUM] =
                make_float2(__fdividef(ac[2], ss[2]), __fdividef(ac[3], ss[3]));
        }
    }
}

extern "C" void kernel_launch(void* const* d_in, const int* in_sizes, int n_in,
                              void* d_out, int out_size)
{
    const float* x     = (const float*)d_in[0];
    const float* wq    = (const float*)d_in[1];
    const float* wk    = (const float*)d_in[2];
    const float* wv    = (const float*)d_in[3];
    const float* h_emb = (const float*)d_in[4];
    const float* w_emb = (const float*)d_in[5];
    float* out = (float*)d_out;

    dim3 grid(WNUM / TW, HNUM / TH, BATCH * G * 2);  // (3, 4, 64) = 768 blocks
    dim3 block(NTHREADS);
    attn_fused_kernel<<<grid, block>>>(x, wq, wk, wv, h_emb, w_emb, out);
}